// round 2
// baseline (speedup 1.0000x reference)
#include <cuda_runtime.h>

#define BB 4
#define CC 64
#define C8 8
#define NN 9216          // 96*96
#define TN 128           // query tile per block
#define TM 64            // key/value chunk
#define SROW 66          // padded smem row stride (floats) for 64-wide tiles

typedef unsigned long long u64;

// ---------------- scratch (no allocs allowed) ----------------
__device__ float g_Q[BB * C8 * NN];              // [b][k][n]
__device__ float g_K[BB * C8 * NN];              // [b][k][n]
__device__ float g_Vt[(size_t)BB * NN * CC];     // [b][n][c]  (transposed V)
__device__ float g_avg[BB * CC];
__device__ float g_mx[BB * CC];
__device__ float g_scale[BB * CC];

// ---------------- f32x2 helpers (FFMA2 path) ----------------
__device__ __forceinline__ u64 f2_fma(u64 a, u64 b, u64 c) {
    u64 d;
    asm("fma.rn.f32x2 %0, %1, %2, %3;" : "=l"(d) : "l"(a), "l"(b), "l"(c));
    return d;
}
__device__ __forceinline__ u64 f2_pack(float lo, float hi) {
    u64 d; asm("mov.b64 %0, {%1, %2};" : "=l"(d) : "f"(lo), "f"(hi)); return d;
}
__device__ __forceinline__ void f2_unpack(u64 v, float &lo, float &hi) {
    asm("mov.b64 {%0, %1}, %2;" : "=f"(lo), "=f"(hi) : "l"(v));
}
__device__ __forceinline__ float sigm(float x) {
    return __fdividef(1.0f, 1.0f + __expf(-x));
}

// ---------------- kernel 1: fused 1x1-conv Q/K/V ----------------
__global__ __launch_bounds__(256) void qkv_kernel(
    const float* __restrict__ x,
    const float* __restrict__ wq, const float* __restrict__ bq,
    const float* __restrict__ wk, const float* __restrict__ bk,
    const float* __restrict__ wv, const float* __restrict__ bv)
{
    __shared__ float sw[80 * 64];  // rows 0..7 wq, 8..15 wk, 16..79 wv
    __shared__ float sb[80];
    int tid = threadIdx.x;
    for (int i = tid; i < 512;  i += 256) sw[i] = wq[i];
    for (int i = tid; i < 512;  i += 256) sw[512 + i] = wk[i];
    for (int i = tid; i < 4096; i += 256) sw[1024 + i] = wv[i];
    if (tid < 80) sb[tid] = (tid < 8) ? bq[tid] : (tid < 16 ? bk[tid - 8] : bv[tid - 16]);
    __syncthreads();

    int n = blockIdx.x * 256 + tid;
    int b = blockIdx.y;
    const float* xb = x + (size_t)b * CC * NN + n;
    float xr[CC];
    #pragma unroll
    for (int c = 0; c < CC; c++) xr[c] = xb[(size_t)c * NN];

    #pragma unroll 1
    for (int o = 0; o < C8; o++) {
        float aq = sb[o], ak = sb[8 + o];
        const float* wqr = sw + o * 64;
        const float* wkr = sw + 512 + o * 64;
        #pragma unroll
        for (int c = 0; c < CC; c++) { aq += wqr[c] * xr[c]; ak += wkr[c] * xr[c]; }
        g_Q[((size_t)b * C8 + o) * NN + n] = aq;
        g_K[((size_t)b * C8 + o) * NN + n] = ak;
    }
    float* vrow = g_Vt + ((size_t)b * NN + n) * CC;
    #pragma unroll 1
    for (int o = 0; o < CC; o++) {
        float av = sb[16 + o];
        const float* wvr = sw + 1024 + o * 64;
        #pragma unroll
        for (int c = 0; c < CC; c++) av += wvr[c] * xr[c];
        vrow[o] = av;
    }
}

// ---------------- kernel 2: fused sigmoid-attention, flash style ----------------
// block: 128 queries x 64 channels output tile; loop over 144 key chunks of 64.
// SMEM layouts chosen so the hot loop's f32x2 loads are natural m-pairs:
//   Vs[c][m] (stride 66), As[n][m] (stride 66) -> LDS.64 conflict-free w/ broadcast.
__global__ __launch_bounds__(256, 2) void attn_kernel(
    const float* __restrict__ x, float* __restrict__ out)
{
    extern __shared__ float sh[];
    float* Qs = sh;                    // [8][128]
    float* Ks = Qs + C8 * TN;          // [8][SROW]
    float* Vs = Ks + C8 * SROW;        // [64][SROW]
    float* As = Vs + CC * SROW;        // [128][SROW]

    int tid = threadIdx.x;
    int b  = blockIdx.y;
    int n0 = blockIdx.x * TN;

    for (int i = tid; i < C8 * TN; i += 256) {
        int kk = i >> 7, nn = i & 127;
        Qs[i] = g_Q[((size_t)b * C8 + kk) * NN + n0 + nn];
    }

    u64 acc[8][4];   // [c-sub][n-sub], each packed over (m even, m odd)
    #pragma unroll
    for (int i = 0; i < 8; i++)
        #pragma unroll
        for (int j = 0; j < 4; j++) acc[i][j] = 0ULL;

    const int cgrp  = tid & 7;          // c = cgrp + 8*i  (interleaved -> no LDS conflicts)
    const int ngrp  = tid >> 3;         // n = n0 + ngrp*4 + j
    const int na    = tid & 127;        // score row this thread computes
    const int mbase = (tid >> 7) * 32;  // score m-range base (2 groups of 32)

    for (int m0 = 0; m0 < NN; m0 += TM) {
        __syncthreads();
        for (int i = tid; i < C8 * TM; i += 256) {
            int kk = i >> 6, mm = i & 63;
            Ks[kk * SROW + mm] = g_K[((size_t)b * C8 + kk) * NN + m0 + mm];
        }
        for (int i = tid; i < CC * TM; i += 256) {
            int mm = i >> 6, cc = i & 63;
            Vs[cc * SROW + mm] = g_Vt[((size_t)b * NN + m0 + mm) * CC + cc];
        }
        __syncthreads();

        // scores: att[na][mbase..mbase+31] = sigmoid(sum_k Q[k][na]*K[k][m])
        #pragma unroll 1
        for (int half = 0; half < 2; half++) {
            u64 e[8];
            #pragma unroll
            for (int p = 0; p < 8; p++) e[p] = 0ULL;
            #pragma unroll
            for (int k = 0; k < C8; k++) {
                float qv = Qs[k * TN + na];
                u64 q2 = f2_pack(qv, qv);
                const u64* krow = (const u64*)(Ks + k * SROW + mbase + half * 16);
                #pragma unroll
                for (int p = 0; p < 8; p++) e[p] = f2_fma(q2, krow[p], e[p]);
            }
            u64* arow = (u64*)(As + na * SROW + mbase + half * 16);
            #pragma unroll
            for (int p = 0; p < 8; p++) {
                float lo, hi; f2_unpack(e[p], lo, hi);
                arow[p] = f2_pack(sigm(lo), sigm(hi));
            }
        }
        __syncthreads();

        // main accumulate: acc[c][n] += V[c][m] * att[n][m], packed over m-pairs
        const u64* a0 = (const u64*)(As + (ngrp * 4 + 0) * SROW);
        const u64* a1 = (const u64*)(As + (ngrp * 4 + 1) * SROW);
        const u64* a2 = (const u64*)(As + (ngrp * 4 + 2) * SROW);
        const u64* a3 = (const u64*)(As + (ngrp * 4 + 3) * SROW);
        #pragma unroll 2
        for (int mp = 0; mp < TM / 2; mp++) {
            u64 av0 = a0[mp], av1 = a1[mp], av2 = a2[mp], av3 = a3[mp];
            #pragma unroll
            for (int i = 0; i < 8; i++) {
                u64 v = *(const u64*)(Vs + (cgrp + 8 * i) * SROW + 2 * mp);
                acc[i][0] = f2_fma(v, av0, acc[i][0]);
                acc[i][1] = f2_fma(v, av1, acc[i][1]);
                acc[i][2] = f2_fma(v, av2, acc[i][2]);
                acc[i][3] = f2_fma(v, av3, acc[i][3]);
            }
        }
    }

    // epilogue: horizontal add of m-pairs, residual, vectorized store
    #pragma unroll
    for (int i = 0; i < 8; i++) {
        int c = cgrp + 8 * i;
        size_t base = ((size_t)b * CC + c) * NN + n0 + ngrp * 4;
        float4 xv = *(const float4*)(x + base);
        float r[4];
        #pragma unroll
        for (int j = 0; j < 4; j++) {
            float lo, hi; f2_unpack(acc[i][j], lo, hi);
            r[j] = lo + hi;
        }
        *(float4*)(out + base) = make_float4(r[0] + xv.x, r[1] + xv.y,
                                             r[2] + xv.z, r[3] + xv.w);
    }
}

// ---------------- kernel 3: per-(b,c) mean & max over N ----------------
__global__ __launch_bounds__(256) void reduce_kernel(const float* __restrict__ out)
{
    __shared__ float ss[256], sm[256];
    int c = blockIdx.x, b = blockIdx.y;
    const float* row = out + ((size_t)b * CC + c) * NN;
    float s = 0.f, m = -3.4e38f;
    for (int i = threadIdx.x; i < NN; i += 256) {
        float v = row[i]; s += v; m = fmaxf(m, v);
    }
    ss[threadIdx.x] = s; sm[threadIdx.x] = m;
    __syncthreads();
    for (int o = 128; o > 0; o >>= 1) {
        if (threadIdx.x < o) {
            ss[threadIdx.x] += ss[threadIdx.x + o];
            sm[threadIdx.x] = fmaxf(sm[threadIdx.x], sm[threadIdx.x + o]);
        }
        __syncthreads();
    }
    if (threadIdx.x == 0) {
        g_avg[b * CC + c] = ss[0] * (1.0f / NN);
        g_mx[b * CC + c]  = sm[0];
    }
}

// ---------------- kernel 4: CBAM MLP -> sigmoid scale ----------------
__global__ __launch_bounds__(256) void scale_kernel(
    const float* __restrict__ w1, const float* __restrict__ w2)
{
    __shared__ float sa[256], sm[256], s1[256], s2[256];
    int tid = threadIdx.x;
    sa[tid] = g_avg[tid]; sm[tid] = g_mx[tid]; s1[tid] = w1[tid]; s2[tid] = w2[tid];
    __syncthreads();
    int b = tid >> 6, c = tid & 63;
    float y = 0.f;
    #pragma unroll
    for (int r = 0; r < 4; r++) {
        float ha = 0.f, hm = 0.f;
        #pragma unroll 16
        for (int cc = 0; cc < 64; cc++) {
            float w = s1[r * 64 + cc];
            ha += w * sa[b * 64 + cc];
            hm += w * sm[b * 64 + cc];
        }
        float wv = s2[c * 4 + r];
        y += wv * fmaxf(ha, 0.f) + wv * fmaxf(hm, 0.f);
    }
    g_scale[tid] = 1.0f / (1.0f + expf(-y));
}

// ---------------- kernel 5: apply channel scale in place ----------------
__global__ __launch_bounds__(256) void apply_scale_kernel(float* __restrict__ out)
{
    int idx = blockIdx.x * 256 + threadIdx.x;
    const int total4 = BB * CC * NN / 4;
    if (idx < total4) {
        int bc = (idx * 4) / NN;   // NN % 4 == 0 -> same (b,c) for all 4 lanes
        float s = g_scale[bc];
        float4 v = ((float4*)out)[idx];
        v.x *= s; v.y *= s; v.z *= s; v.w *= s;
        ((float4*)out)[idx] = v;
    }
}

// ---------------- launch ----------------
extern "C" void kernel_launch(void* const* d_in, const int* in_sizes, int n_in,
                              void* d_out, int out_size)
{
    const float* x     = (const float*)d_in[0];
    const float* wq    = (const float*)d_in[1];
    const float* bq    = (const float*)d_in[2];
    const float* wk    = (const float*)d_in[3];
    const float* bk    = (const float*)d_in[4];
    const float* wv    = (const float*)d_in[5];
    const float* bv    = (const float*)d_in[6];
    const float* ca_w1 = (const float*)d_in[7];
    const float* ca_w2 = (const float*)d_in[8];
    float* out = (float*)d_out;

    const int smem_bytes = (C8 * TN + C8 * SROW + CC * SROW + TN * SROW) * 4; // 56896
    cudaFuncSetAttribute(attn_kernel, cudaFuncAttributeMaxDynamicSharedMemorySize, smem_bytes);

    qkv_kernel<<<dim3(NN / 256, BB), 256>>>(x, wq, bq, wk, bk, wv, bv);
    attn_kernel<<<dim3(NN / TN, BB), 256, smem_bytes>>>(x, out);
    reduce_kernel<<<dim3(CC, BB), 256>>>(out);
    scale_kernel<<<1, 256>>>(ca_w1, ca_w2);
    apply_scale_kernel<<<(BB * CC * NN / 4 + 255) / 256, 256>>>(out);
}

// round 4
// speedup vs baseline: 3.1563x; 3.1563x over previous
#include <cuda_runtime.h>
#include <cstdint>

#define BB 4
#define CC 64
#define C8 8
#define NN 9216          // 96*96
#define TN 128           // queries per CTA
#define TM 64            // key/value chunk
#define NCHUNK (NN/TM)   // 144
#define ST 72            // smem row stride (floats)

// ---------------- scratch ----------------
__device__ float g_Qn[(size_t)BB * NN * C8];          // [b][n][k]
__device__ float g_Kp[(size_t)BB * NCHUNK * C8 * TM]; // [b][ch][k][m]  (tiled)
__device__ float g_Vp[(size_t)BB * NCHUNK * CC * TM]; // [b][ch][c][m'] (tiled, m-permuted)
__device__ float g_avg[BB * CC];
__device__ float g_mx [BB * CC];
__device__ float g_scale[BB * CC];

__device__ __forceinline__ float to_tf32(float v) {
    asm("cvt.rna.tf32.f32 %0, %0;" : "+f"(v));
    return v;
}
__device__ __forceinline__ float sigm(float x) {
    return __fdividef(1.0f, 1.0f + __expf(-x));
}
__device__ __forceinline__ uint32_t fb(float v) { return __float_as_uint(v); }

// m16n8k8 tf32 MMA, D=C accumulate in fp32
__device__ __forceinline__ void mma8(float d[4], const uint32_t a[4], const uint32_t b[2]) {
    asm volatile(
        "mma.sync.aligned.m16n8k8.row.col.f32.tf32.tf32.f32 "
        "{%0,%1,%2,%3}, {%4,%5,%6,%7}, {%8,%9}, {%0,%1,%2,%3};"
        : "+f"(d[0]), "+f"(d[1]), "+f"(d[2]), "+f"(d[3])
        : "r"(a[0]), "r"(a[1]), "r"(a[2]), "r"(a[3]), "r"(b[0]), "r"(b[1]));
}

// ---------------- kernel 1: fused 1x1-conv Q/K/V with pre-tiling ----------------
__global__ __launch_bounds__(256) void qkv_kernel(
    const float* __restrict__ x,
    const float* __restrict__ wq, const float* __restrict__ bq,
    const float* __restrict__ wk, const float* __restrict__ bk,
    const float* __restrict__ wv, const float* __restrict__ bv)
{
    __shared__ float sw[80 * 64];
    __shared__ float sb[80];
    int tid = threadIdx.x;
    for (int i = tid; i < 512;  i += 256) sw[i] = wq[i];
    for (int i = tid; i < 512;  i += 256) sw[512 + i] = wk[i];
    for (int i = tid; i < 4096; i += 256) sw[1024 + i] = wv[i];
    if (tid < 80) sb[tid] = (tid < 8) ? bq[tid] : (tid < 16 ? bk[tid - 8] : bv[tid - 16]);
    __syncthreads();

    int n = blockIdx.x * 256 + tid;
    int b = blockIdx.y;
    const float* xb = x + (size_t)b * CC * NN + n;
    float xr[CC];
    #pragma unroll
    for (int c = 0; c < CC; c++) xr[c] = xb[(size_t)c * NN];

    const int ch = n >> 6;
    const int ml = n & 63;
    const int mp = (ml & ~7) | (((ml & 3) << 1) | ((ml >> 2) & 1)); // within-8 perm

    float* qrow = g_Qn + ((size_t)b * NN + n) * C8;
    float* ktile = g_Kp + ((size_t)(b * NCHUNK + ch) * C8) * TM;
    #pragma unroll 1
    for (int o = 0; o < C8; o++) {
        float aq = sb[o], ak = sb[8 + o];
        const float* wqr = sw + o * 64;
        const float* wkr = sw + 512 + o * 64;
        #pragma unroll
        for (int c = 0; c < CC; c++) { aq += wqr[c] * xr[c]; ak += wkr[c] * xr[c]; }
        qrow[o] = to_tf32(aq);
        ktile[o * TM + ml] = to_tf32(ak);
    }
    float* vtile = g_Vp + ((size_t)(b * NCHUNK + ch) * CC) * TM;
    #pragma unroll 1
    for (int o = 0; o < CC; o++) {
        float av = sb[16 + o];
        const float* wvr = sw + 1024 + o * 64;
        #pragma unroll
        for (int c = 0; c < CC; c++) av += wvr[c] * xr[c];
        vtile[o * TM + mp] = to_tf32(av);
    }
}

// ---------------- kernel 2: tf32 mma.sync fused sigmoid-attention ----------------
// 8 warps: warp w -> n rows [(w>>1)*32, +32) (2 n-frags), half h=w&1:
//   GEMM1 covers m in [32h, 32h+32); GEMM2 covers c in [32h, 32h+32).
__global__ __launch_bounds__(256, 2) void attn_mma_kernel(
    const float* __restrict__ x, float* __restrict__ out)
{
    extern __shared__ float sh[];
    float* Ks = sh;                 // [8][ST]
    float* Vs = Ks + C8 * ST;       // [64][ST]  (m within 8 permuted)
    float* As = Vs + CC * ST;       // [128][ST] (m within 8 permuted)

    const int tid = threadIdx.x, wid = tid >> 5, lid = tid & 31;
    const int g = lid >> 2, t = lid & 3;
    const int b = blockIdx.y, n0 = blockIdx.x * TN;
    const int nb0 = (wid >> 1) * 32;
    const int h = wid & 1;

    const int r0 = 2 * t, r1 = 2 * t + 1;
    const int p0 = ((r0 & 3) << 1) | (r0 >> 2);
    const int p1 = ((r1 & 3) << 1) | (r1 >> 2);

    // Q A-fragments (persist whole kernel)
    uint32_t qa[2][4];
    #pragma unroll
    for (int nf = 0; nf < 2; nf++) {
        const float* q0 = g_Qn + ((size_t)b * NN + n0 + nb0 + nf * 16 + g) * C8;
        qa[nf][0] = fb(q0[t]);
        qa[nf][1] = fb(q0[8 * C8 + t]);
        qa[nf][2] = fb(q0[t + 4]);
        qa[nf][3] = fb(q0[8 * C8 + t + 4]);
    }

    float acc[2][4][4];
    #pragma unroll
    for (int nf = 0; nf < 2; nf++)
        #pragma unroll
        for (int j = 0; j < 4; j++)
            #pragma unroll
            for (int k = 0; k < 4; k++) acc[nf][j][k] = 0.0f;

    const float* ktile = g_Kp + (size_t)b * NCHUNK * C8 * TM;
    const float* vtile = g_Vp + (size_t)b * NCHUNK * CC * TM;

    for (int ch = 0; ch < NCHUNK; ch++) {
        __syncthreads();
        // stage K: 512 floats, linear copy
        if (tid < 128) {
            float4 kv = *(const float4*)(ktile + (size_t)ch * C8 * TM + tid * 4);
            int k = tid >> 4, m = (tid & 15) * 4;
            *(float4*)(Ks + k * ST + m) = kv;
        }
        // stage V: 4096 floats, linear copy
        const float* vt = vtile + (size_t)ch * CC * TM;
        #pragma unroll
        for (int r = 0; r < 4; r++) {
            int f4 = tid + r * 256;
            float4 vv = *(const float4*)(vt + f4 * 4);
            int c = f4 >> 4, m = (f4 & 15) * 4;
            *(float4*)(Vs + c * ST + m) = vv;
        }
        __syncthreads();

        // GEMM1: energy frags e[nf][mt][4] over m in [32h, 32h+32)
        float e[2][4][4];
        #pragma unroll
        for (int nf = 0; nf < 2; nf++)
            #pragma unroll
            for (int mt = 0; mt < 4; mt++)
                #pragma unroll
                for (int k = 0; k < 4; k++) e[nf][mt][k] = 0.0f;
        #pragma unroll
        for (int mt = 0; mt < 4; mt++) {
            int mm = h * 32 + mt * 8;
            uint32_t kb[2];
            kb[0] = fb(Ks[t * ST + mm + g]);
            kb[1] = fb(Ks[(t + 4) * ST + mm + g]);
            mma8(e[0][mt], qa[0], kb);
            mma8(e[1][mt], qa[1], kb);
        }

        // sigmoid -> tf32 -> As (permuted columns)
        #pragma unroll
        for (int nf = 0; nf < 2; nf++) {
            int n = nb0 + nf * 16 + g;
            #pragma unroll
            for (int mt = 0; mt < 4; mt++) {
                int cb = h * 32 + mt * 8;
                float* a0 = As + n * ST + cb;
                float* a1 = As + (n + 8) * ST + cb;
                a0[p0] = to_tf32(sigm(e[nf][mt][0]));
                a0[p1] = to_tf32(sigm(e[nf][mt][1]));
                a1[p0] = to_tf32(sigm(e[nf][mt][2]));
                a1[p1] = to_tf32(sigm(e[nf][mt][3]));
            }
        }
        __syncthreads();

        // GEMM2: acc[n, c in [32h,32h+32)] += att * V
        #pragma unroll
        for (int ks = 0; ks < 8; ks++) {
            uint32_t af[2][4];
            #pragma unroll
            for (int nf = 0; nf < 2; nf++) {
                int n = nb0 + nf * 16 + g;
                float2 v01 = *(const float2*)(As + n * ST + ks * 8 + 2 * t);
                float2 v23 = *(const float2*)(As + (n + 8) * ST + ks * 8 + 2 * t);
                af[nf][0] = fb(v01.x); af[nf][1] = fb(v23.x);
                af[nf][2] = fb(v01.y); af[nf][3] = fb(v23.y);
            }
            #pragma unroll
            for (int j = 0; j < 4; j++) {
                int c = h * 32 + j * 8 + g;
                float2 bv = *(const float2*)(Vs + c * ST + ks * 8 + 2 * t);
                uint32_t bf[2] = { fb(bv.x), fb(bv.y) };
                mma8(acc[0][j], af[0], bf);
                mma8(acc[1][j], af[1], bf);
            }
        }
    }

    // epilogue: residual + store. acc frag (nf, j): rows n, n+8; cols c=32h+8j+2t, +1
    #pragma unroll
    for (int nf = 0; nf < 2; nf++) {
        int n = n0 + nb0 + nf * 16 + g;
        #pragma unroll
        for (int j = 0; j < 4; j++) {
            int c = h * 32 + j * 8 + 2 * t;
            size_t i00 = ((size_t)b * CC + c) * NN + n;
            size_t i01 = i00 + NN;                 // c+1
            out[i00]     = acc[nf][j][0] + x[i00];
            out[i01]     = acc[nf][j][1] + x[i01];
            out[i00 + 8] = acc[nf][j][2] + x[i00 + 8];   // n+8
            out[i01 + 8] = acc[nf][j][3] + x[i01 + 8];
        }
    }
}

// ---------------- kernel 3: per-(b,c) mean & max over N ----------------
__global__ __launch_bounds__(256) void reduce_kernel(const float* __restrict__ out)
{
    __shared__ float ss[256], sm[256];
    int c = blockIdx.x, b = blockIdx.y;
    const float* row = out + ((size_t)b * CC + c) * NN;
    float s = 0.f, m = -3.4e38f;
    for (int i = threadIdx.x; i < NN; i += 256) {
        float v = row[i]; s += v; m = fmaxf(m, v);
    }
    ss[threadIdx.x] = s; sm[threadIdx.x] = m;
    __syncthreads();
    for (int o = 128; o > 0; o >>= 1) {
        if (threadIdx.x < o) {
            ss[threadIdx.x] += ss[threadIdx.x + o];
            sm[threadIdx.x] = fmaxf(sm[threadIdx.x], sm[threadIdx.x + o]);
        }
        __syncthreads();
    }
    if (threadIdx.x == 0) {
        g_avg[b * CC + c] = ss[0] * (1.0f / NN);
        g_mx[b * CC + c]  = sm[0];
    }
}

// ---------------- kernel 4: CBAM MLP -> sigmoid scale ----------------
__global__ __launch_bounds__(256) void scale_kernel(
    const float* __restrict__ w1, const float* __restrict__ w2)
{
    __shared__ float sa[256], sm[256], s1[256], s2[256];
    int tid = threadIdx.x;
    sa[tid] = g_avg[tid]; sm[tid] = g_mx[tid]; s1[tid] = w1[tid]; s2[tid] = w2[tid];
    __syncthreads();
    int b = tid >> 6, c = tid & 63;
    float y = 0.f;
    #pragma unroll
    for (int r = 0; r < 4; r++) {
        float ha = 0.f, hm = 0.f;
        #pragma unroll 16
        for (int cc = 0; cc < 64; cc++) {
            float w = s1[r * 64 + cc];
            ha += w * sa[b * 64 + cc];
            hm += w * sm[b * 64 + cc];
        }
        float wv = s2[c * 4 + r];
        y += wv * fmaxf(ha, 0.f) + wv * fmaxf(hm, 0.f);
    }
    g_scale[tid] = 1.0f / (1.0f + expf(-y));
}

// ---------------- kernel 5: apply channel scale in place ----------------
__global__ __launch_bounds__(256) void apply_scale_kernel(float* __restrict__ out)
{
    int idx = blockIdx.x * 256 + threadIdx.x;
    const int total4 = BB * CC * NN / 4;
    if (idx < total4) {
        int bc = (idx * 4) / NN;
        float s = g_scale[bc];
        float4 v = ((float4*)out)[idx];
        v.x *= s; v.y *= s; v.z *= s; v.w *= s;
        ((float4*)out)[idx] = v;
    }
}

// ---------------- launch ----------------
extern "C" void kernel_launch(void* const* d_in, const int* in_sizes, int n_in,
                              void* d_out, int out_size)
{
    const float* x     = (const float*)d_in[0];
    const float* wq    = (const float*)d_in[1];
    const float* bq    = (const float*)d_in[2];
    const float* wk    = (const float*)d_in[3];
    const float* bk    = (const float*)d_in[4];
    const float* wv    = (const float*)d_in[5];
    const float* bv    = (const float*)d_in[6];
    const float* ca_w1 = (const float*)d_in[7];
    const float* ca_w2 = (const float*)d_in[8];
    float* out = (float*)d_out;

    const int smem_bytes = (C8 + CC + TN) * ST * sizeof(float);  // 57600
    cudaFuncSetAttribute(attn_mma_kernel, cudaFuncAttributeMaxDynamicSharedMemorySize, smem_bytes);

    qkv_kernel<<<dim3(NN / 256, BB), 256>>>(x, wq, bq, wk, bk, wv, bv);
    attn_mma_kernel<<<dim3(NN / TN, BB), 256, smem_bytes>>>(x, out);
    reduce_kernel<<<dim3(CC, BB), 256>>>(out);
    scale_kernel<<<1, 256>>>(ca_w1, ca_w2);
    apply_scale_kernel<<<(BB * CC * NN / 4 + 255) / 256, 256>>>(out);
}

// round 5
// speedup vs baseline: 7.5188x; 2.3821x over previous
#include <cuda_runtime.h>
#include <cuda_fp16.h>
#include <cstdint>

#define BB 4
#define CC 64
#define C8 8
#define NN 9216          // 96*96
#define TN 128           // queries per CTA
#define TM 64            // key/value chunk
#define NCHUNK (NN/TM)   // 144
#define KST 72           // Ks row stride (floats)
#define VST 80           // Vs row stride (halfs) = 40 words, 160B

// ---------------- scratch ----------------
__device__ float  g_Qn[(size_t)BB * NN * C8];          // [b][n][k] tf32
__device__ float  g_Kp[(size_t)BB * NCHUNK * C8 * TM]; // [b][ch][k][m] tf32
__device__ __half g_Vp[(size_t)BB * NCHUNK * CC * TM]; // [b][ch][c][m'] f16, m perm within 16
__device__ float  g_avg[BB * CC];
__device__ float  g_mx [BB * CC];
__device__ float  g_scale[BB * CC];

__device__ __forceinline__ float to_tf32(float v) {
    asm("cvt.rna.tf32.f32 %0, %0;" : "+f"(v));
    return v;
}
__device__ __forceinline__ float sg(float x) {       // sigmoid via MUFU.TANH
    float t = 0.5f * x;
    asm("tanh.approx.f32 %0, %0;" : "+f"(t));
    return fmaf(t, 0.5f, 0.5f);
}
__device__ __forceinline__ uint32_t pk(float lo, float hi) {  // f16x2 {lo,hi}
    uint32_t r;
    asm("cvt.rn.f16x2.f32 %0, %1, %2;" : "=r"(r) : "f"(hi), "f"(lo));
    return r;
}
__device__ __forceinline__ uint32_t fb(float v) { return __float_as_uint(v); }
__device__ __forceinline__ uint32_t smem_u32(const void* p) {
    uint32_t a;
    asm("{ .reg .u64 t; cvta.to.shared.u64 t, %1; cvt.u32.u64 %0, t; }" : "=r"(a) : "l"(p));
    return a;
}

// m16n8k8 tf32
__device__ __forceinline__ void mma8(float d[4], const uint32_t a[4], uint32_t b0, uint32_t b1) {
    asm volatile(
        "mma.sync.aligned.m16n8k8.row.col.f32.tf32.tf32.f32 "
        "{%0,%1,%2,%3}, {%4,%5,%6,%7}, {%8,%9}, {%0,%1,%2,%3};"
        : "+f"(d[0]), "+f"(d[1]), "+f"(d[2]), "+f"(d[3])
        : "r"(a[0]), "r"(a[1]), "r"(a[2]), "r"(a[3]), "r"(b0), "r"(b1));
}
// m16n8k16 f16 -> f32
__device__ __forceinline__ void mma16(float d[4], const uint32_t a[4], uint32_t b0, uint32_t b1) {
    asm volatile(
        "mma.sync.aligned.m16n8k16.row.col.f32.f16.f16.f32 "
        "{%0,%1,%2,%3}, {%4,%5,%6,%7}, {%8,%9}, {%0,%1,%2,%3};"
        : "+f"(d[0]), "+f"(d[1]), "+f"(d[2]), "+f"(d[3])
        : "r"(a[0]), "r"(a[1]), "r"(a[2]), "r"(a[3]), "r"(b0), "r"(b1));
}

#define CP16(dst, src) \
    asm volatile("cp.async.cg.shared.global [%0], [%1], 16;" :: "r"(dst), "l"(src))
#define CP_COMMIT() asm volatile("cp.async.commit_group;" ::: "memory")
#define CP_WAIT0()  asm volatile("cp.async.wait_group 0;" ::: "memory")

// ---------------- kernel 1: fused 1x1-conv Q/K/V with pre-tiling ----------------
__global__ __launch_bounds__(256) void qkv_kernel(
    const float* __restrict__ x,
    const float* __restrict__ wq, const float* __restrict__ bq,
    const float* __restrict__ wk, const float* __restrict__ bk,
    const float* __restrict__ wv, const float* __restrict__ bv)
{
    __shared__ float sw[80 * 64];
    __shared__ float sb[80];
    int tid = threadIdx.x;
    for (int i = tid; i < 512;  i += 256) sw[i] = wq[i];
    for (int i = tid; i < 512;  i += 256) sw[512 + i] = wk[i];
    for (int i = tid; i < 4096; i += 256) sw[1024 + i] = wv[i];
    if (tid < 80) sb[tid] = (tid < 8) ? bq[tid] : (tid < 16 ? bk[tid - 8] : bv[tid - 16]);
    __syncthreads();

    int n = blockIdx.x * 256 + tid;
    int b = blockIdx.y;
    const float* xb = x + (size_t)b * CC * NN + n;
    float xr[CC];
    #pragma unroll
    for (int c = 0; c < CC; c++) xr[c] = xb[(size_t)c * NN];

    const int ch = n >> 6;
    const int m  = n & 63;
    // f16 pair-interleave perm within 16-block: pair P -> phys word (P&3)*2+(P>>2)
    const int P = (m & 15) >> 1;
    const int mphys = (m & ~15) | ((((P & 3) * 2 + (P >> 2)) << 1) | (m & 1));

    float* qrow  = g_Qn + ((size_t)b * NN + n) * C8;
    float* ktile = g_Kp + ((size_t)(b * NCHUNK + ch) * C8) * TM;
    #pragma unroll 1
    for (int o = 0; o < C8; o++) {
        float aq = sb[o], ak = sb[8 + o];
        const float* wqr = sw + o * 64;
        const float* wkr = sw + 512 + o * 64;
        #pragma unroll
        for (int c = 0; c < CC; c++) { aq += wqr[c] * xr[c]; ak += wkr[c] * xr[c]; }
        qrow[o] = to_tf32(aq);
        ktile[o * TM + m] = to_tf32(ak);
    }
    __half* vtile = g_Vp + ((size_t)(b * NCHUNK + ch) * CC) * TM;
    #pragma unroll 1
    for (int o = 0; o < CC; o++) {
        float av = sb[16 + o];
        const float* wvr = sw + 1024 + o * 64;
        #pragma unroll
        for (int c = 0; c < CC; c++) av += wvr[c] * xr[c];
        vtile[o * TM + mphys] = __float2half_rn(av);
    }
}

// ---------------- kernel 2: fused sigmoid-attention (tf32 QK, f16 att*V) --------
// 8 warps; warp w owns n rows [w*16, w*16+16), all 64 m per chunk.
// GEMM1 accumulators (sigmoided, f16x2-packed) become GEMM2 A-fragments in regs.
__global__ __launch_bounds__(256, 2) void attn_mma_kernel(
    const float* __restrict__ x, float* __restrict__ out)
{
    __shared__ float  Ks[2][C8 * KST];    // 4608 B
    __shared__ __half Vs[2][CC * VST];    // 20480 B

    const int tid = threadIdx.x, wid = tid >> 5, lid = tid & 31;
    const int g = lid >> 2, t = lid & 3;
    const int b = blockIdx.y, n0 = blockIdx.x * TN;

    const uint32_t ksb = smem_u32(&Ks[0][0]);
    const uint32_t vsb = smem_u32(&Vs[0][0]);

    // Q A-fragment (persistent)
    uint32_t qa[4];
    {
        const float* q0 = g_Qn + ((size_t)b * NN + n0 + wid * 16 + g) * C8;
        qa[0] = fb(q0[t]);
        qa[1] = fb(q0[8 * C8 + t]);
        qa[2] = fb(q0[t + 4]);
        qa[3] = fb(q0[8 * C8 + t + 4]);
    }

    float acc[8][4];
    #pragma unroll
    for (int j = 0; j < 8; j++)
        #pragma unroll
        for (int k = 0; k < 4; k++) acc[j][k] = 0.0f;

    const float*  kbase = g_Kp + (size_t)b * NCHUNK * C8 * TM;
    const __half* vbase = g_Vp + (size_t)b * NCHUNK * CC * TM;

    // staging: K = 128 x 16B pieces, V = 512 x 16B pieces
    auto stage = [&](int ch, int p) {
        if (tid < 128) {
            int k = tid >> 4, seg = tid & 15;
            CP16(ksb + (uint32_t)(p * C8 * KST * 4 + k * (KST * 4) + seg * 16),
                 (const char*)(kbase + (size_t)ch * C8 * TM + k * TM) + seg * 16);
        }
        #pragma unroll
        for (int r = 0; r < 2; r++) {
            int pc = tid + r * 256;
            int c = pc >> 3, seg = pc & 7;
            CP16(vsb + (uint32_t)(p * CC * VST * 2 + c * (VST * 2) + seg * 16),
                 (const char*)(vbase + (size_t)ch * CC * TM + c * TM) + seg * 16);
        }
    };

    stage(0, 0);
    CP_COMMIT();

    for (int ch = 0; ch < NCHUNK; ch++) {
        const int p = ch & 1;
        CP_WAIT0();
        __syncthreads();
        if (ch + 1 < NCHUNK) { stage(ch + 1, p ^ 1); CP_COMMIT(); }

        // GEMM1: e[mt] = Q.K^T for m-tile mt (8 tiles of 8)
        float e[8][4];
        #pragma unroll
        for (int mt = 0; mt < 8; mt++) {
            e[mt][0] = e[mt][1] = e[mt][2] = e[mt][3] = 0.0f;
            uint32_t b0 = fb(Ks[p][t * KST + mt * 8 + g]);
            uint32_t b1 = fb(Ks[p][(t + 4) * KST + mt * 8 + g]);
            mma8(e[mt], qa, b0, b1);
        }

        // sigmoid + pack straight into GEMM2 A-fragments (registers)
        uint32_t af[4][4];
        #pragma unroll
        for (int ks = 0; ks < 4; ks++) {
            af[ks][0] = pk(sg(e[2 * ks][0]),     sg(e[2 * ks][1]));
            af[ks][1] = pk(sg(e[2 * ks][2]),     sg(e[2 * ks][3]));
            af[ks][2] = pk(sg(e[2 * ks + 1][0]), sg(e[2 * ks + 1][1]));
            af[ks][3] = pk(sg(e[2 * ks + 1][2]), sg(e[2 * ks + 1][3]));
        }

        // GEMM2: acc[n16 x c64] += att * V   (f16, B-frags = LDS.64, conflict-free)
        #pragma unroll
        for (int ks = 0; ks < 4; ks++) {
            #pragma unroll
            for (int j = 0; j < 8; j++) {
                uint2 bv = *(const uint2*)(&Vs[p][(8 * j + g) * VST + ks * 16 + 4 * t]);
                mma16(acc[j], af[ks], bv.x, bv.y);
            }
        }
    }

    // epilogue: residual + store
    #pragma unroll
    for (int j = 0; j < 8; j++) {
        int n = n0 + wid * 16 + g;
        int c = 8 * j + 2 * t;
        size_t i00 = ((size_t)b * CC + c) * NN + n;
        size_t i01 = i00 + NN;
        out[i00]     = acc[j][0] + x[i00];
        out[i01]     = acc[j][1] + x[i01];
        out[i00 + 8] = acc[j][2] + x[i00 + 8];
        out[i01 + 8] = acc[j][3] + x[i01 + 8];
    }
}

// ---------------- kernel 3: per-(b,c) mean & max over N ----------------
__global__ __launch_bounds__(256) void reduce_kernel(const float* __restrict__ out)
{
    __shared__ float ss[256], sm[256];
    int c = blockIdx.x, b = blockIdx.y;
    const float* row = out + ((size_t)b * CC + c) * NN;
    float s = 0.f, m = -3.4e38f;
    for (int i = threadIdx.x; i < NN / 4; i += 256) {
        float4 v = ((const float4*)row)[i];
        s += (v.x + v.y) + (v.z + v.w);
        m = fmaxf(m, fmaxf(fmaxf(v.x, v.y), fmaxf(v.z, v.w)));
    }
    ss[threadIdx.x] = s; sm[threadIdx.x] = m;
    __syncthreads();
    for (int o = 128; o > 0; o >>= 1) {
        if (threadIdx.x < o) {
            ss[threadIdx.x] += ss[threadIdx.x + o];
            sm[threadIdx.x] = fmaxf(sm[threadIdx.x], sm[threadIdx.x + o]);
        }
        __syncthreads();
    }
    if (threadIdx.x == 0) {
        g_avg[b * CC + c] = ss[0] * (1.0f / NN);
        g_mx[b * CC + c]  = sm[0];
    }
}

// ---------------- kernel 4: CBAM MLP -> sigmoid scale ----------------
__global__ __launch_bounds__(256) void scale_kernel(
    const float* __restrict__ w1, const float* __restrict__ w2)
{
    __shared__ float sa[256], sm[256], s1[256], s2[256];
    int tid = threadIdx.x;
    sa[tid] = g_avg[tid]; sm[tid] = g_mx[tid]; s1[tid] = w1[tid]; s2[tid] = w2[tid];
    __syncthreads();
    int b = tid >> 6, c = tid & 63;
    float y = 0.f;
    #pragma unroll
    for (int r = 0; r < 4; r++) {
        float ha = 0.f, hm = 0.f;
        #pragma unroll 16
        for (int cc = 0; cc < 64; cc++) {
            float w = s1[r * 64 + cc];
            ha += w * sa[b * 64 + cc];
            hm += w * sm[b * 64 + cc];
        }
        float wv = s2[c * 4 + r];
        y += wv * fmaxf(ha, 0.f) + wv * fmaxf(hm, 0.f);
    }
    g_scale[tid] = 1.0f / (1.0f + expf(-y));
}

// ---------------- kernel 5: apply channel scale in place ----------------
__global__ __launch_bounds__(256) void apply_scale_kernel(float* __restrict__ out)
{
    int idx = blockIdx.x * 256 + threadIdx.x;
    const int total4 = BB * CC * NN / 4;
    if (idx < total4) {
        int bc = (idx * 4) / NN;
        float s = g_scale[bc];
        float4 v = ((float4*)out)[idx];
        v.x *= s; v.y *= s; v.z *= s; v.w *= s;
        ((float4*)out)[idx] = v;
    }
}

// ---------------- launch ----------------
extern "C" void kernel_launch(void* const* d_in, const int* in_sizes, int n_in,
                              void* d_out, int out_size)
{
    const float* x     = (const float*)d_in[0];
    const float* wq    = (const float*)d_in[1];
    const float* bq    = (const float*)d_in[2];
    const float* wk    = (const float*)d_in[3];
    const float* bk    = (const float*)d_in[4];
    const float* wv    = (const float*)d_in[5];
    const float* bv    = (const float*)d_in[6];
    const float* ca_w1 = (const float*)d_in[7];
    const float* ca_w2 = (const float*)d_in[8];
    float* out = (float*)d_out;

    qkv_kernel<<<dim3(NN / 256, BB), 256>>>(x, wq, bq, wk, bk, wv, bv);
    attn_mma_kernel<<<dim3(NN / TN, BB), 256>>>(x, out);
    reduce_kernel<<<dim3(CC, BB), 256>>>(out);
    scale_kernel<<<1, 256>>>(ca_w1, ca_w2);
    apply_scale_kernel<<<(BB * CC * NN / 4 + 255) / 256, 256>>>(out);
}